// round 6
// baseline (speedup 1.0000x reference)
#include <cuda_runtime.h>
#include <math.h>

#define B_    16
#define L_    400
#define T_    200
#define NMELS 80
#define ENC   512
#define PRE   256
#define QHD   1024
#define ATTN_ 128
#define NFILT 32
#define NBLK  148
#define NTHR  256

// ---- scratch (device globals; allocation forbidden) ----
__device__ __align__(16) float g_dec_ins[T_ * B_ * PRE];
__device__ __align__(16) float g_h1[B_ * T_ * PRE];
__device__ __align__(16) float g_pm[B_ * L_ * ATTN_];
__device__ __align__(16) float g_cl[B_ * L_ * NFILT];
__device__ __align__(16) float g_energy[B_ * L_];
__device__ __align__(16) float g_qh[2][B_ * QHD];
__device__ __align__(16) float g_qc[B_ * QHD];
__device__ __align__(16) float g_dh[2][B_ * QHD];
__device__ __align__(16) float g_dc[B_ * QHD];
__device__ __align__(16) float g_ctx[B_ * ENC];
__device__ __align__(16) float g_aw[B_ * L_];
__device__ __align__(16) float g_aws[B_ * L_];
__device__ unsigned g_count;   // zero-init; returns to 0 at end of every run
__device__ unsigned g_gen;     // monotonic; works from any start value

// ---- software grid barrier (all NBLK blocks resident: grid <= SM count) ----
__device__ __forceinline__ void grid_sync() {
    __syncthreads();
    if (threadIdx.x == 0) {
        volatile unsigned* vg = &g_gen;
        unsigned gen = *vg;
        __threadfence();                       // release: drain stores, gpu scope
        if (atomicAdd(&g_count, 1u) == NBLK - 1) {
            g_count = 0u;
            __threadfence();
            atomicAdd(&g_gen, 1u);             // release flag
        } else {
            while (*vg == gen) __nanosleep(64);
        }
        __threadfence();                       // acquire: CCTL.IVALL flushes L1D
    }
    __syncthreads();
}

__device__ __forceinline__ float sigmoidf_(float z) { return 1.f / (1.f + expf(-z)); }

// warp computes 2 rows x 16 batches; x batch-stride == len (len % 128 == 0)
__device__ __forceinline__ void gemv_seg2(const float* __restrict__ x, int len,
                                          const float* __restrict__ w0,
                                          const float* __restrict__ w1,
                                          int lane, float acc0[16], float acc1[16]) {
    for (int ch = 0; ch < (len >> 7); ++ch) {
        int k = (ch << 7) + (lane << 2);
        float4 a = *(const float4*)(w0 + k);
        float4 c = *(const float4*)(w1 + k);
        const float* xp = x + k;
        #pragma unroll
        for (int b = 0; b < 16; ++b) {
            float4 xv = *(const float4*)(xp + b * len);
            acc0[b] += a.x * xv.x + a.y * xv.y + a.z * xv.z + a.w * xv.w;
            acc1[b] += c.x * xv.x + c.y * xv.y + c.z * xv.z + c.w * xv.w;
        }
    }
}

// one unit-group (4 units, all 4 gates) of an LSTM cell, fused update
__device__ __forceinline__ void lstm_group(
    const float* __restrict__ x0, int n0, const float* __restrict__ x1, int n1,
    const float* __restrict__ hp, float* __restrict__ ho, float* __restrict__ cb,
    const float* __restrict__ wih, int kih, const float* __restrict__ whh,
    const float* __restrict__ bih, const float* __restrict__ bhh,
    int u0, float* sh) {
    int tid = threadIdx.x, lane = tid & 31, w = tid >> 5;
    int g = w & 3, lu = (w >> 2) * 2;
    int r0 = g * 1024 + u0 + lu, r1 = r0 + 1;
    float acc0[16], acc1[16];
    #pragma unroll
    for (int b = 0; b < 16; ++b) { acc0[b] = 0.f; acc1[b] = 0.f; }
    gemv_seg2(x0, n0, wih + (size_t)r0 * kih,      wih + (size_t)r1 * kih,      lane, acc0, acc1);
    gemv_seg2(x1, n1, wih + (size_t)r0 * kih + n0, wih + (size_t)r1 * kih + n0, lane, acc0, acc1);
    gemv_seg2(hp, QHD, whh + (size_t)r0 * QHD,     whh + (size_t)r1 * QHD,      lane, acc0, acc1);
    #pragma unroll
    for (int off = 16; off > 0; off >>= 1) {
        #pragma unroll
        for (int b = 0; b < 16; ++b) {
            acc0[b] += __shfl_xor_sync(0xffffffffu, acc0[b], off);
            acc1[b] += __shfl_xor_sync(0xffffffffu, acc1[b], off);
        }
    }
    // sh used as [gate][unit(4)][b(16)]
    if (lane < 16) {
        sh[(g * 4 + lu) * 16 + lane]       = acc0[lane];
        sh[(g * 4 + lu + 1) * 16 + lane]   = acc1[lane];
    }
    __syncthreads();
    if (tid < 64) {
        int b = tid & 15, ui = tid >> 4, u = u0 + ui;
        float zi = sh[(0 * 4 + ui) * 16 + b] + bih[u]        + bhh[u];
        float zf = sh[(1 * 4 + ui) * 16 + b] + bih[1024 + u] + bhh[1024 + u];
        float zg = sh[(2 * 4 + ui) * 16 + b] + bih[2048 + u] + bhh[2048 + u];
        float zo = sh[(3 * 4 + ui) * 16 + b] + bih[3072 + u] + bhh[3072 + u];
        float cc = sigmoidf_(zf) * cb[b * 1024 + u] + sigmoidf_(zi) * tanhf(zg);
        cb[b * 1024 + u] = cc;
        ho[b * 1024 + u] = sigmoidf_(zo) * tanhf(cc);
    }
    __syncthreads();
}

// conv task: one (b, 100-l tile)
__device__ __forceinline__ void conv_block(const float* __restrict__ conv, int idx, float* sh) {
    int tid = threadIdx.x;
    float* hist = sh;          // 2 x 132
    float* cv = sh + 264;      // 32 x 62
    int b = idx >> 2, l0 = (idx & 3) * 100;
    __syncthreads();
    for (int j = tid; j < 2 * 130; j += NTHR) {
        int c = j / 130, jj = j % 130, pos = l0 - 15 + jj;
        float v = 0.f;
        if (pos >= 0 && pos < L_) v = (c == 0) ? g_aw[b * L_ + pos] : g_aws[b * L_ + pos];
        hist[c * 132 + jj] = v;
    }
    for (int i = tid; i < NFILT * 62; i += NTHR) cv[i] = conv[i];
    __syncthreads();
    int f = tid & 31, lr = tid >> 5;
    const float* cf0 = cv + f * 62;
    const float* cf1 = cf0 + 31;
    for (int l = l0 + lr; l < l0 + 100; l += 8) {
        int base = l - l0;
        float s = 0.f;
        #pragma unroll
        for (int k = 0; k < 31; ++k)
            s += hist[base + k] * cf0[k] + hist[132 + base + k] * cf1[k];
        g_cl[((size_t)b * L_ + l) * NFILT + f] = s;
    }
}

// energy for (b, 50-l tile), with per-block pq recompute
__device__ __forceinline__ void energy_block(
    const float* __restrict__ wq, const float* __restrict__ wloc,
    const float* __restrict__ av, const float* __restrict__ hq_all,
    int blk, float* sh) {
    int tid = threadIdx.x, lane = tid & 31, w = tid >> 5;
    int b = blk >> 3, l0 = (blk & 7) * 50;
    float* wlT = sh;             // 4096
    float* pqs = sh + 4096;      // 128
    float* vs  = sh + 4224;      // 128
    float* cls = sh + 4352;      // 8 x 32
    // pq[b][r] = qh[b] . wq[r]
    const float4* xq = (const float4*)(hq_all + (size_t)b * QHD);
    for (int i = 0; i < 16; ++i) {
        int r = w * 16 + i;
        const float4* wr = (const float4*)(wq + (size_t)r * QHD);
        float acc = 0.f;
        #pragma unroll
        for (int k = 0; k < 8; ++k) {
            float4 a = wr[lane + k * 32], x = xq[lane + k * 32];
            acc += a.x * x.x + a.y * x.y + a.z * x.z + a.w * x.w;
        }
        #pragma unroll
        for (int off = 16; off > 0; off >>= 1) acc += __shfl_xor_sync(0xffffffffu, acc, off);
        if (lane == 0) pqs[r] = acc;
    }
    for (int i = tid; i < ATTN_ * NFILT; i += NTHR)
        wlT[(i & 31) * ATTN_ + (i >> 5)] = wloc[i];        // wloc is [a][f]
    if (tid < ATTN_) vs[tid] = av[tid];
    __syncthreads();
    for (int l = l0 + w; l < l0 + 50; l += 8) {
        cls[w * 32 + lane] = g_cl[((size_t)b * L_ + l) * NFILT + lane];
        __syncwarp();
        const float* pmr = g_pm + ((size_t)b * L_ + l) * ATTN_;
        float s0 = pqs[lane]      + pmr[lane];
        float s1 = pqs[lane + 32] + pmr[lane + 32];
        float s2 = pqs[lane + 64] + pmr[lane + 64];
        float s3 = pqs[lane + 96] + pmr[lane + 96];
        #pragma unroll
        for (int f = 0; f < NFILT; ++f) {
            float clf = cls[w * 32 + f];
            const float* wr = wlT + f * ATTN_;
            s0 += clf * wr[lane];       s1 += clf * wr[lane + 32];
            s2 += clf * wr[lane + 64];  s3 += clf * wr[lane + 96];
        }
        float e = tanhf(s0) * vs[lane] + tanhf(s1) * vs[lane + 32] +
                  tanhf(s2) * vs[lane + 64] + tanhf(s3) * vs[lane + 96];
        #pragma unroll
        for (int off = 16; off > 0; off >>= 1) e += __shfl_xor_sync(0xffffffffu, e, off);
        if (lane == 0) g_energy[b * L_ + l] = e;
        __syncwarp();
    }
    __syncthreads();
}

// softmax over L then context, one block per batch
__device__ __forceinline__ void softmax_ctx(const float* __restrict__ memory, int b, int t,
                                            float* __restrict__ out_align, float* sh) {
    int tid = threadIdx.x;
    float* sv = sh;            // 400
    float* red = sh + 512;     // 256
    float m = -1e30f;
    for (int l = tid; l < L_; l += NTHR) { float e = g_energy[b * L_ + l]; sv[l] = e; m = fmaxf(m, e); }
    red[tid] = m; __syncthreads();
    for (int s = 128; s > 0; s >>= 1) { if (tid < s) red[tid] = fmaxf(red[tid], red[tid + s]); __syncthreads(); }
    m = red[0]; __syncthreads();
    float sum = 0.f;
    for (int l = tid; l < L_; l += NTHR) { float ex = expf(sv[l] - m); sv[l] = ex; sum += ex; }
    red[tid] = sum; __syncthreads();
    for (int s = 128; s > 0; s >>= 1) { if (tid < s) red[tid] += red[tid + s]; __syncthreads(); }
    float inv = 1.f / red[0];
    __syncthreads();
    for (int l = tid; l < L_; l += NTHR) {
        float wv = sv[l] * inv; sv[l] = wv;
        g_aw[b * L_ + l] = wv;
        g_aws[b * L_ + l] += wv;
        out_align[((size_t)b * T_ + t) * L_ + l] = wv;
    }
    __syncthreads();
    float acc0 = 0.f, acc1 = 0.f;
    const float* mp = memory + (size_t)b * L_ * ENC;
    #pragma unroll 4
    for (int l = 0; l < L_; ++l) {
        float wv = sv[l];
        acc0 += wv * mp[(size_t)l * ENC + tid];
        acc1 += wv * mp[(size_t)l * ENC + tid + 256];
    }
    g_ctx[b * ENC + tid] = acc0;
    g_ctx[b * ENC + tid + 256] = acc1;
    __syncthreads();
}

// output projection for step tprev (6 blocks: blkL = 0..5 covers rows 0..95, 81 used)
__device__ __forceinline__ void out_proj(
    const float* __restrict__ proj_w, const float* __restrict__ proj_b,
    const float* __restrict__ gate_w, const float* __restrict__ gate_b,
    int tprev, int blkL, float* __restrict__ out_mel, float* __restrict__ out_stop) {
    int tid = threadIdx.x, lane = tid & 31, w = tid >> 5;
    const float* dh = g_dh[(tprev + 1) & 1];
    int r0 = blkL * 16 + w * 2;
    for (int rr = 0; rr < 2; ++rr) {
        int r = r0 + rr;
        if (r > 80) break;
        const float* wr = (r < 80) ? proj_w + (size_t)r * (QHD + ENC) : gate_w;
        float acc[16];
        #pragma unroll
        for (int b = 0; b < 16; ++b) acc[b] = 0.f;
        for (int ch = 0; ch < 8; ++ch) {                 // dh segment (1024)
            int k = (ch << 7) + (lane << 2);
            float4 a = *(const float4*)(wr + k);
            #pragma unroll
            for (int b = 0; b < 16; ++b) {
                float4 xv = *(const float4*)(dh + b * 1024 + k);
                acc[b] += a.x * xv.x + a.y * xv.y + a.z * xv.z + a.w * xv.w;
            }
        }
        for (int ch = 0; ch < 4; ++ch) {                 // ctx segment (512)
            int k = (ch << 7) + (lane << 2);
            float4 a = *(const float4*)(wr + 1024 + k);
            #pragma unroll
            for (int b = 0; b < 16; ++b) {
                float4 xv = *(const float4*)(g_ctx + b * 512 + k);
                acc[b] += a.x * xv.x + a.y * xv.y + a.z * xv.z + a.w * xv.w;
            }
        }
        #pragma unroll
        for (int off = 16; off > 0; off >>= 1) {
            #pragma unroll
            for (int b = 0; b < 16; ++b) acc[b] += __shfl_xor_sync(0xffffffffu, acc[b], off);
        }
        if (lane < 16) {
            int b = lane;
            if (r < 80) out_mel[((size_t)b * T_ + tprev) * NMELS + r] = acc[b] + proj_b[r];
            else        out_stop[(size_t)b * T_ + tprev] = sigmoidf_(acc[b] + gate_b[0]);
        }
    }
}

__global__ __launch_bounds__(NTHR) void decoder_kernel(
    const float* __restrict__ memory, const float* __restrict__ teacher,
    const float* __restrict__ pre_w1, const float* __restrict__ pre_w2,
    const float* __restrict__ q_wih, const float* __restrict__ q_whh,
    const float* __restrict__ q_bih, const float* __restrict__ q_bhh,
    const float* __restrict__ d_wih, const float* __restrict__ d_whh,
    const float* __restrict__ d_bih, const float* __restrict__ d_bhh,
    const float* __restrict__ wq, const float* __restrict__ conv,
    const float* __restrict__ wloc, const float* __restrict__ av,
    const float* __restrict__ wm,
    const float* __restrict__ proj_w, const float* __restrict__ proj_b,
    const float* __restrict__ gate_w, const float* __restrict__ gate_b,
    float* __restrict__ out_mel, float* __restrict__ out_align,
    float* __restrict__ out_stop) {
    __shared__ __align__(16) float sh[8448];          // 33 KB, reused per phase
    int blk = blockIdx.x, tid = threadIdx.x;

    // ---- S1: zero state + prenet layer 1 ----
    for (int i = blk * NTHR + tid; i < B_ * QHD; i += NBLK * NTHR) {
        g_qh[0][i] = 0.f; g_qc[i] = 0.f; g_dh[0][i] = 0.f; g_dc[i] = 0.f;
    }
    for (int i = blk * NTHR + tid; i < B_ * ENC; i += NBLK * NTHR) g_ctx[i] = 0.f;
    for (int i = blk * NTHR + tid; i < B_ * L_; i += NBLK * NTHR) { g_aw[i] = 0.f; g_aws[i] = 0.f; }
    for (int i = blk * NTHR + tid; i < B_ * PRE; i += NBLK * NTHR) g_dec_ins[i] = 0.f;

    for (int tile = blk; tile < 200; tile += NBLK) {
        __syncthreads();
        int r0 = tile * 16;
        for (int i = tid; i < 16 * NMELS; i += NTHR) sh[i] = teacher[(size_t)r0 * NMELS + i];
        __syncthreads();
        const float* wr = pre_w1 + (size_t)tid * NMELS;
        for (int r = 0; r < 16; ++r) {
            float acc = 0.f;
            #pragma unroll
            for (int m = 0; m < NMELS; ++m) acc += sh[r * NMELS + m] * wr[m];
            g_h1[(size_t)(r0 + r) * PRE + tid] = fmaxf(acc, 0.f);
        }
    }
    grid_sync();

    // ---- S2: prenet layer 2 (-> dec_ins) + processed_memory ----
    for (int tt = blk; tt < 199; tt += NBLK) {
        int t = tt + 1;
        __syncthreads();
        for (int i = tid; i < 16 * PRE; i += NTHR)
            sh[i] = g_h1[((size_t)(i >> 8) * T_ + (t - 1)) * PRE + (i & 255)];
        __syncthreads();
        const float4* wr4 = (const float4*)(pre_w2 + (size_t)tid * PRE);
        for (int bb = 0; bb < 16; ++bb) {
            const float4* sx4 = (const float4*)(sh + bb * PRE);
            float acc = 0.f;
            #pragma unroll 8
            for (int k = 0; k < PRE / 4; ++k) {
                float4 a = wr4[k], x = sx4[k];
                acc += a.x * x.x + a.y * x.y + a.z * x.z + a.w * x.w;
            }
            g_dec_ins[((size_t)t * B_ + bb) * PRE + tid] = fmaxf(acc, 0.f);
        }
    }
    for (int tile = blk; tile < 400; tile += NBLK) {
        __syncthreads();
        int r0 = tile * 16;
        for (int i = tid; i < 16 * ENC; i += NTHR) sh[i] = memory[(size_t)r0 * ENC + i];
        __syncthreads();
        int a = tid & 127, half = tid >> 7;
        const float4* wr4 = (const float4*)(wm + (size_t)a * ENC);
        for (int rr = 0; rr < 8; ++rr) {
            int r = half * 8 + rr;
            const float4* sx4 = (const float4*)(sh + r * ENC);
            float acc = 0.f;
            #pragma unroll 8
            for (int k = 0; k < ENC / 4; ++k) {
                float4 aa = wr4[k], x = sx4[k];
                acc += aa.x * x.x + aa.y * x.y + aa.z * x.z + aa.w * x.w;
            }
            g_pm[(size_t)(r0 + r) * ATTN_ + a] = acc;
        }
    }
    grid_sync();

    // ---- decode loop ----
    for (int t = 0; t < T_; ++t) {
        // P_A: qLSTM || out(t-1) || conv
        if (blk < 128) {
            const float* x0 = g_dec_ins + (size_t)t * B_ * PRE;
            const float* hp = g_qh[t & 1];
            float* ho = g_qh[(t + 1) & 1];
            for (int ug = blk; ug < 256; ug += 128)
                lstm_group(x0, PRE, g_ctx, ENC, hp, ho, g_qc,
                           q_wih, PRE + ENC, q_whh, q_bih, q_bhh, ug * 4, sh);
        } else if (blk < 134) {
            if (t > 0) out_proj(proj_w, proj_b, gate_w, gate_b, t - 1, blk - 128, out_mel, out_stop);
        } else {
            for (int idx = blk - 134; idx < 64; idx += 14) conv_block(conv, idx, sh);
        }
        grid_sync();
        // P_B: energies
        if (blk < 128) energy_block(wq, wloc, av, g_qh[(t + 1) & 1], blk, sh);
        grid_sync();
        // P_C: softmax + context
        if (blk < B_) softmax_ctx(memory, blk, t, out_align, sh);
        grid_sync();
        // P_D: dec LSTM
        if (blk < 128) {
            const float* hqn = g_qh[(t + 1) & 1];
            const float* hp = g_dh[t & 1];
            float* ho = g_dh[(t + 1) & 1];
            for (int ug = blk; ug < 256; ug += 128)
                lstm_group(g_ctx, ENC, hqn, QHD, hp, ho, g_dc,
                           d_wih, ENC + QHD, d_whh, d_bih, d_bhh, ug * 4, sh);
        }
        grid_sync();
    }
    // final output projection for t = T-1
    if (blk >= 128 && blk < 134)
        out_proj(proj_w, proj_b, gate_w, gate_b, T_ - 1, blk - 128, out_mel, out_stop);
}

extern "C" void kernel_launch(void* const* d_in, const int* in_sizes, int n_in,
                              void* d_out, int out_size) {
    (void)in_sizes; (void)n_in; (void)out_size;
    const float* memory  = (const float*)d_in[0];
    // d_in[1] memory_lengths unused (mask = None in reference)
    const float* teacher = (const float*)d_in[2];
    const float* pre_w1  = (const float*)d_in[3];
    const float* pre_w2  = (const float*)d_in[4];
    const float* q_wih   = (const float*)d_in[5];
    const float* q_whh   = (const float*)d_in[6];
    const float* q_bih   = (const float*)d_in[7];
    const float* q_bhh   = (const float*)d_in[8];
    const float* d_wih   = (const float*)d_in[9];
    const float* d_whh   = (const float*)d_in[10];
    const float* d_bih   = (const float*)d_in[11];
    const float* d_bhh   = (const float*)d_in[12];
    const float* attn_wq   = (const float*)d_in[13];
    const float* attn_wm   = (const float*)d_in[14];
    const float* attn_conv = (const float*)d_in[15];
    const float* attn_wloc = (const float*)d_in[16];
    const float* attn_v    = (const float*)d_in[17];
    const float* proj_w  = (const float*)d_in[18];
    const float* proj_b  = (const float*)d_in[19];
    const float* gate_w  = (const float*)d_in[20];
    const float* gate_b  = (const float*)d_in[21];

    float* out_mel   = (float*)d_out;
    float* out_align = out_mel + (size_t)B_ * T_ * NMELS;
    float* out_stop  = out_align + (size_t)B_ * T_ * L_;

    decoder_kernel<<<NBLK, NTHR>>>(
        memory, teacher, pre_w1, pre_w2,
        q_wih, q_whh, q_bih, q_bhh,
        d_wih, d_whh, d_bih, d_bhh,
        attn_wq, attn_conv, attn_wloc, attn_v, attn_wm,
        proj_w, proj_b, gate_w, gate_b,
        out_mel, out_align, out_stop);
}

// round 7
// speedup vs baseline: 1.4714x; 1.4714x over previous
#include <cuda_runtime.h>
#include <math.h>

#define B_    16
#define L_    400
#define T_    200
#define NMELS 80
#define ENC   512
#define PRE   256
#define QHD   1024
#define ATTN_ 128
#define NFILT 32
#define NBLK  148
#define NTHR  512
#define SMEM_BYTES 163840   // dLSTM staging: 16 * 2560 * 4

// ---- scratch (device globals; allocation forbidden) ----
__device__ __align__(16) float g_dec_ins[T_ * B_ * PRE];
__device__ __align__(16) float g_h1[B_ * T_ * PRE];
__device__ __align__(16) float g_pm[B_ * L_ * ATTN_];
__device__ __align__(16) float g_cl[B_ * L_ * NFILT];
__device__ __align__(16) float g_p[B_ * L_];       // exp(energy), unnormalized
__device__ __align__(16) float g_psum[B_ * 8];     // per-tile partial sums
__device__ __align__(16) float g_qh[2][B_ * QHD];
__device__ __align__(16) float g_qc[B_ * QHD];
__device__ __align__(16) float g_dh[2][B_ * QHD];
__device__ __align__(16) float g_dc[B_ * QHD];
__device__ __align__(16) float g_ctx[B_ * ENC];
__device__ __align__(16) float g_aw[B_ * L_];
__device__ __align__(16) float g_aws[B_ * L_];
__device__ unsigned g_count;   // returns to 0 after every run
__device__ unsigned g_gen;     // monotonic; any start value works

// ---- software grid barrier (grid == 148 <= SM count, all co-resident) ----
__device__ __forceinline__ void grid_sync() {
    __syncthreads();
    if (threadIdx.x == 0) {
        volatile unsigned* vg = &g_gen;
        unsigned gen = *vg;
        __threadfence();
        if (atomicAdd(&g_count, 1u) == NBLK - 1) {
            g_count = 0u;
            __threadfence();
            atomicAdd(&g_gen, 1u);
        } else {
            while (*vg == gen) __nanosleep(32);
        }
        __threadfence();
    }
    __syncthreads();
}

__device__ __forceinline__ float sigmoidf_(float z) { return 1.f / (1.f + expf(-z)); }

// copy 16 rows of len floats (global row stride glen) into smem xs at column
// offset coff, smem row stride KTOT
__device__ __forceinline__ void stage16(float* xs, int KTOT, int coff,
                                        const float* __restrict__ src, int glen, int len) {
    int n4 = len >> 2;
    for (int idx = threadIdx.x; idx < 16 * n4; idx += NTHR) {
        int b = idx / n4, k4 = idx - b * n4;
        *(float4*)(xs + b * KTOT + coff + (k4 << 2)) =
            *(const float4*)(src + (size_t)b * glen + (k4 << 2));
    }
}

// warp computes 2 rows x 16 batches; x in SMEM at xs + b*KTOT + xoff
__device__ __forceinline__ void gemv_s2(const float* xs, int KTOT, int xoff, int len,
                                        const float* __restrict__ w0,
                                        const float* __restrict__ w1,
                                        int lane, float acc0[16], float acc1[16]) {
    for (int ch = 0; ch < (len >> 7); ++ch) {
        int k = (ch << 7) + (lane << 2);
        float4 a = *(const float4*)(w0 + k);
        float4 c = *(const float4*)(w1 + k);
        const float* xp = xs + xoff + k;
        #pragma unroll
        for (int b = 0; b < 16; ++b) {
            float4 xv = *(const float4*)(xp + b * KTOT);
            acc0[b] += a.x * xv.x + a.y * xv.y + a.z * xv.z + a.w * xv.w;
            acc1[b] += c.x * xv.x + c.y * xv.y + c.z * xv.z + c.w * xv.w;
        }
    }
}

// full LSTM cell slice: block handles 8 units (32 rows), 16 warps x 2 rows
__device__ __forceinline__ void lstm_phase(const float* xs, int KTOT, int n0, int n1,
        const float* __restrict__ wih, const float* __restrict__ whh,
        const float* __restrict__ bih, const float* __restrict__ bhh,
        float* __restrict__ ho, float* __restrict__ cb, int blk, float* shz) {
    int tid = threadIdx.x, lane = tid & 31, w = tid >> 5;
    int g = w & 3, lu = (w >> 2) * 2;
    int u0 = blk * 8, kih = n0 + n1;
    int r0 = g * 1024 + u0 + lu, r1 = r0 + 1;
    float acc0[16], acc1[16];
    #pragma unroll
    for (int b = 0; b < 16; ++b) { acc0[b] = 0.f; acc1[b] = 0.f; }
    gemv_s2(xs, KTOT, 0,  n0,   wih + (size_t)r0 * kih,      wih + (size_t)r1 * kih,      lane, acc0, acc1);
    gemv_s2(xs, KTOT, n0, n1,   wih + (size_t)r0 * kih + n0, wih + (size_t)r1 * kih + n0, lane, acc0, acc1);
    gemv_s2(xs, KTOT, kih, QHD, whh + (size_t)r0 * QHD,      whh + (size_t)r1 * QHD,      lane, acc0, acc1);
    #pragma unroll
    for (int off = 16; off > 0; off >>= 1) {
        #pragma unroll
        for (int b = 0; b < 16; ++b) {
            acc0[b] += __shfl_xor_sync(0xffffffffu, acc0[b], off);
            acc1[b] += __shfl_xor_sync(0xffffffffu, acc1[b], off);
        }
    }
    if (lane < 16) {
        shz[(g * 8 + lu) * 16 + lane]     = acc0[lane];
        shz[(g * 8 + lu + 1) * 16 + lane] = acc1[lane];
    }
    __syncthreads();
    if (tid < 128) {
        int b = tid & 15, ui = tid >> 4, u = u0 + ui;
        float zi = shz[(0 * 8 + ui) * 16 + b] + bih[u]        + bhh[u];
        float zf = shz[(1 * 8 + ui) * 16 + b] + bih[1024 + u] + bhh[1024 + u];
        float zg = shz[(2 * 8 + ui) * 16 + b] + bih[2048 + u] + bhh[2048 + u];
        float zo = shz[(3 * 8 + ui) * 16 + b] + bih[3072 + u] + bhh[3072 + u];
        float cc = sigmoidf_(zf) * cb[b * 1024 + u] + sigmoidf_(zi) * tanhf(zg);
        cb[b * 1024 + u] = cc;
        ho[b * 1024 + u] = sigmoidf_(zo) * tanhf(cc);
    }
    __syncthreads();
}

// location conv, one (b, 100-l tile) task
__device__ __forceinline__ void conv_block(const float* __restrict__ conv, int idx, float* dsh) {
    int tid = threadIdx.x;
    float* hist = dsh;          // 2 x 132
    float* cv = dsh + 264;      // 32 x 62
    int b = idx >> 2, l0 = (idx & 3) * 100;
    __syncthreads();
    for (int j = tid; j < 2 * 130; j += NTHR) {
        int c = j / 130, jj = j - c * 130, pos = l0 - 15 + jj;
        float v = 0.f;
        if (pos >= 0 && pos < L_) v = (c == 0) ? g_aw[b * L_ + pos] : g_aws[b * L_ + pos];
        hist[c * 132 + jj] = v;
    }
    for (int i = tid; i < NFILT * 62; i += NTHR) cv[i] = conv[i];
    __syncthreads();
    int f = tid & 31, lr = tid >> 5;            // 16 l-lanes
    const float* cf0 = cv + f * 62;
    const float* cf1 = cf0 + 31;
    for (int l = l0 + lr; l < l0 + 100; l += 16) {
        int base = l - l0;
        float s = 0.f;
        #pragma unroll
        for (int k = 0; k < 31; ++k)
            s += hist[base + k] * cf0[k] + hist[132 + base + k] * cf1[k];
        g_cl[((size_t)b * L_ + l) * NFILT + f] = s;
    }
}

// energy for (b, 50-l tile): p = exp(v . tanh(pq + pm + cl@wloc^T)), partial sums
__device__ __forceinline__ void energy_phase(
        const float* __restrict__ wq, const float* __restrict__ wloc,
        const float* __restrict__ av, const float* __restrict__ hq_all,
        int blk, float* dsh) {
    int tid = threadIdx.x, lane = tid & 31, w = tid >> 5;
    int b = blk >> 3, tile = blk & 7, l0 = tile * 50;
    float* wlT = dsh;             // 4096  [f][a]
    float* pqs = dsh + 4096;      // 128
    float* vs  = dsh + 4224;      // 128
    float* cls = dsh + 4352;      // 16 x 32
    float* red = dsh + 4864;      // 16
    const float4* xq = (const float4*)(hq_all + (size_t)b * QHD);
    for (int i = 0; i < 8; ++i) {
        int r = w * 8 + i;
        const float4* wr = (const float4*)(wq + (size_t)r * QHD);
        float acc = 0.f;
        #pragma unroll
        for (int k = 0; k < 8; ++k) {
            float4 a = wr[lane + k * 32], x = xq[lane + k * 32];
            acc += a.x * x.x + a.y * x.y + a.z * x.z + a.w * x.w;
        }
        #pragma unroll
        for (int off = 16; off > 0; off >>= 1) acc += __shfl_xor_sync(0xffffffffu, acc, off);
        if (lane == 0) pqs[r] = acc;
    }
    for (int i = tid; i < ATTN_ * NFILT; i += NTHR)
        wlT[(i & 31) * ATTN_ + (i >> 5)] = wloc[i];          // wloc is [a][f]
    if (tid < ATTN_) vs[tid] = av[tid];
    __syncthreads();
    float psum = 0.f;
    for (int l = l0 + w; l < l0 + 50; l += 16) {
        cls[w * 32 + lane] = g_cl[((size_t)b * L_ + l) * NFILT + lane];
        __syncwarp();
        const float* pmr = g_pm + ((size_t)b * L_ + l) * ATTN_;
        float s0 = pqs[lane]      + pmr[lane];
        float s1 = pqs[lane + 32] + pmr[lane + 32];
        float s2 = pqs[lane + 64] + pmr[lane + 64];
        float s3 = pqs[lane + 96] + pmr[lane + 96];
        #pragma unroll
        for (int f = 0; f < NFILT; ++f) {
            float clf = cls[w * 32 + f];
            const float* wr = wlT + f * ATTN_;
            s0 += clf * wr[lane];       s1 += clf * wr[lane + 32];
            s2 += clf * wr[lane + 64];  s3 += clf * wr[lane + 96];
        }
        float e = tanhf(s0) * vs[lane] + tanhf(s1) * vs[lane + 32] +
                  tanhf(s2) * vs[lane + 64] + tanhf(s3) * vs[lane + 96];
        #pragma unroll
        for (int off = 16; off > 0; off >>= 1) e += __shfl_xor_sync(0xffffffffu, e, off);
        if (lane == 0) {
            float p = expf(e);            // |e| <= sum|v| ~ 5: safe without max-sub
            g_p[b * L_ + l] = p;
            psum += p;
        }
        __syncwarp();
    }
    if (lane == 0) red[w] = psum;
    __syncthreads();
    if (tid == 0) {
        float s = 0.f;
        #pragma unroll
        for (int i = 0; i < 16; ++i) s += red[i];
        g_psum[b * 8 + tile] = s;
    }
    __syncthreads();
}

// ctx for (b, 64-col slice) + normalize weights / aws / alignments
__device__ __forceinline__ void ctx_phase(const float* __restrict__ memory, int blk, int t,
                                          float* __restrict__ out_align, float* dsh) {
    int tid = threadIdx.x;
    int b = blk >> 3, tile = blk & 7, e0 = tile * 64;
    float* sp = dsh;            // 400
    float* sred = dsh + 512;    // 8 x 64
    for (int l = tid; l < L_; l += NTHR) sp[l] = g_p[b * L_ + l];
    float S = 0.f;
    #pragma unroll
    for (int i = 0; i < 8; ++i) S += g_psum[b * 8 + i];
    float inv = 1.f / S;
    __syncthreads();
    int e = tid & 63, part = tid >> 6;   // 8 l-partitions
    const float* mp = memory + ((size_t)b * L_) * ENC + e0 + e;
    float acc = 0.f;
    int lbeg = part * 50;
    #pragma unroll 5
    for (int l = lbeg; l < lbeg + 50; ++l) acc += sp[l] * mp[(size_t)l * ENC];
    sred[part * 64 + e] = acc;
    __syncthreads();
    if (part == 0) {
        float s = 0.f;
        #pragma unroll
        for (int i = 0; i < 8; ++i) s += sred[i * 64 + e];
        g_ctx[b * ENC + e0 + e] = s * inv;
    }
    if (tid < 50) {
        int l = tile * 50 + tid;
        float wv = sp[l] * inv;
        g_aw[b * L_ + l] = wv;
        g_aws[b * L_ + l] += wv;
        out_align[((size_t)b * T_ + t) * L_ + l] = wv;
    }
    __syncthreads();
}

// output projection for step tprev; 3 blocks x 32 rows cover 81 rows
__device__ __forceinline__ void out_proj(
        const float* __restrict__ proj_w, const float* __restrict__ proj_b,
        const float* __restrict__ gate_w, const float* __restrict__ gate_b,
        int tprev, int blkL, float* __restrict__ out_mel, float* __restrict__ out_stop) {
    int tid = threadIdx.x, lane = tid & 31, w = tid >> 5;
    const float* dh = g_dh[(tprev + 1) & 1];
    int r0 = blkL * 32 + w * 2;
    for (int rr = 0; rr < 2; ++rr) {
        int r = r0 + rr;
        if (r > 80) break;
        const float* wr = (r < 80) ? proj_w + (size_t)r * (QHD + ENC) : gate_w;
        float acc[16];
        #pragma unroll
        for (int b = 0; b < 16; ++b) acc[b] = 0.f;
        for (int ch = 0; ch < 8; ++ch) {
            int k = (ch << 7) + (lane << 2);
            float4 a = *(const float4*)(wr + k);
            #pragma unroll
            for (int b = 0; b < 16; ++b) {
                float4 xv = *(const float4*)(dh + b * 1024 + k);
                acc[b] += a.x * xv.x + a.y * xv.y + a.z * xv.z + a.w * xv.w;
            }
        }
        for (int ch = 0; ch < 4; ++ch) {
            int k = (ch << 7) + (lane << 2);
            float4 a = *(const float4*)(wr + 1024 + k);
            #pragma unroll
            for (int b = 0; b < 16; ++b) {
                float4 xv = *(const float4*)(g_ctx + b * 512 + k);
                acc[b] += a.x * xv.x + a.y * xv.y + a.z * xv.z + a.w * xv.w;
            }
        }
        #pragma unroll
        for (int off = 16; off > 0; off >>= 1) {
            #pragma unroll
            for (int b = 0; b < 16; ++b) acc[b] += __shfl_xor_sync(0xffffffffu, acc[b], off);
        }
        if (lane < 16) {
            int b = lane;
            if (r < 80) out_mel[((size_t)b * T_ + tprev) * NMELS + r] = acc[b] + proj_b[r];
            else        out_stop[(size_t)b * T_ + tprev] = sigmoidf_(acc[b] + gate_b[0]);
        }
    }
}

__global__ __launch_bounds__(NTHR, 1) void decoder_kernel(
    const float* __restrict__ memory, const float* __restrict__ teacher,
    const float* __restrict__ pre_w1, const float* __restrict__ pre_w2,
    const float* __restrict__ q_wih, const float* __restrict__ q_whh,
    const float* __restrict__ q_bih, const float* __restrict__ q_bhh,
    const float* __restrict__ d_wih, const float* __restrict__ d_whh,
    const float* __restrict__ d_bih, const float* __restrict__ d_bhh,
    const float* __restrict__ wq, const float* __restrict__ conv,
    const float* __restrict__ wloc, const float* __restrict__ av,
    const float* __restrict__ wm,
    const float* __restrict__ proj_w, const float* __restrict__ proj_b,
    const float* __restrict__ gate_w, const float* __restrict__ gate_b,
    float* __restrict__ out_mel, float* __restrict__ out_align,
    float* __restrict__ out_stop) {
    extern __shared__ __align__(16) float dsh[];
    __shared__ __align__(16) float shz[512];
    int blk = blockIdx.x, tid = threadIdx.x;

    // ---- S1: zero state + prenet layer 1 ----
    for (int i = blk * NTHR + tid; i < B_ * QHD; i += NBLK * NTHR) {
        g_qh[0][i] = 0.f; g_qc[i] = 0.f; g_dh[0][i] = 0.f; g_dc[i] = 0.f;
    }
    for (int i = blk * NTHR + tid; i < B_ * ENC; i += NBLK * NTHR) g_ctx[i] = 0.f;
    for (int i = blk * NTHR + tid; i < B_ * L_; i += NBLK * NTHR) { g_aw[i] = 0.f; g_aws[i] = 0.f; }
    for (int i = blk * NTHR + tid; i < B_ * PRE; i += NBLK * NTHR) g_dec_ins[i] = 0.f;

    for (int tile = blk; tile < 200; tile += NBLK) {
        __syncthreads();
        int r0 = tile * 16;
        for (int i = tid; i < 16 * NMELS; i += NTHR) dsh[i] = teacher[(size_t)r0 * NMELS + i];
        __syncthreads();
        int j = tid & 255, rh = tid >> 8;
        const float* wr = pre_w1 + (size_t)j * NMELS;
        for (int r = rh * 8; r < rh * 8 + 8; ++r) {
            float acc = 0.f;
            #pragma unroll
            for (int m = 0; m < NMELS; ++m) acc += dsh[r * NMELS + m] * wr[m];
            g_h1[(size_t)(r0 + r) * PRE + j] = fmaxf(acc, 0.f);
        }
    }
    grid_sync();

    // ---- S2: prenet layer 2 + processed_memory ----
    for (int tt = blk; tt < 199; tt += NBLK) {
        int t = tt + 1;
        __syncthreads();
        for (int i = tid; i < 16 * PRE; i += NTHR)
            dsh[i] = g_h1[((size_t)(i >> 8) * T_ + (t - 1)) * PRE + (i & 255)];
        __syncthreads();
        int j = tid & 255, rh = tid >> 8;
        const float4* wr4 = (const float4*)(pre_w2 + (size_t)j * PRE);
        for (int bb = rh * 8; bb < rh * 8 + 8; ++bb) {
            const float4* sx4 = (const float4*)(dsh + bb * PRE);
            float acc = 0.f;
            #pragma unroll 8
            for (int k = 0; k < PRE / 4; ++k) {
                float4 a = wr4[k], x = sx4[k];
                acc += a.x * x.x + a.y * x.y + a.z * x.z + a.w * x.w;
            }
            g_dec_ins[((size_t)t * B_ + bb) * PRE + j] = fmaxf(acc, 0.f);
        }
    }
    for (int tile = blk; tile < 400; tile += NBLK) {
        __syncthreads();
        int r0 = tile * 16;
        for (int i = tid; i < 16 * ENC; i += NTHR) dsh[i] = memory[(size_t)r0 * ENC + i];
        __syncthreads();
        int a = tid & 127, q = tid >> 7;
        const float4* wr4 = (const float4*)(wm + (size_t)a * ENC);
        for (int r = q * 4; r < q * 4 + 4; ++r) {
            const float4* sx4 = (const float4*)(dsh + r * ENC);
            float acc = 0.f;
            #pragma unroll 8
            for (int k = 0; k < ENC / 4; ++k) {
                float4 aa = wr4[k], x = sx4[k];
                acc += aa.x * x.x + aa.y * x.y + aa.z * x.z + aa.w * x.w;
            }
            g_pm[(size_t)(r0 + r) * ATTN_ + a] = acc;
        }
    }
    grid_sync();

    // ---- decode loop ----
    for (int t = 0; t < T_; ++t) {
        // P_A: qLSTM || out(t-1) || conv
        if (blk < 128) {
            stage16(dsh, 1792, 0,   g_dec_ins + (size_t)t * B_ * PRE, PRE, PRE);
            stage16(dsh, 1792, 256, g_ctx, ENC, ENC);
            stage16(dsh, 1792, 768, g_qh[t & 1], QHD, QHD);
            __syncthreads();
            lstm_phase(dsh, 1792, PRE, ENC, q_wih, q_whh, q_bih, q_bhh,
                       g_qh[(t + 1) & 1], g_qc, blk, shz);
        } else if (blk < 131) {
            if (t > 0) out_proj(proj_w, proj_b, gate_w, gate_b, t - 1, blk - 128, out_mel, out_stop);
        } else {
            for (int idx = blk - 131; idx < 64; idx += 17) conv_block(conv, idx, dsh);
        }
        grid_sync();
        // P_B: energies -> exp + partial sums
        if (blk < 128) energy_phase(wq, wloc, av, g_qh[(t + 1) & 1], blk, dsh);
        grid_sync();
        // P_C: ctx + normalize weights
        if (blk < 128) ctx_phase(memory, blk, t, out_align, dsh);
        grid_sync();
        // P_D: dec LSTM
        if (blk < 128) {
            stage16(dsh, 2560, 0,    g_ctx, ENC, ENC);
            stage16(dsh, 2560, 512,  g_qh[(t + 1) & 1], QHD, QHD);
            stage16(dsh, 2560, 1536, g_dh[t & 1], QHD, QHD);
            __syncthreads();
            lstm_phase(dsh, 2560, ENC, QHD, d_wih, d_whh, d_bih, d_bhh,
                       g_dh[(t + 1) & 1], g_dc, blk, shz);
        }
        grid_sync();
    }
    if (blk >= 128 && blk < 131)
        out_proj(proj_w, proj_b, gate_w, gate_b, T_ - 1, blk - 128, out_mel, out_stop);
}

extern "C" void kernel_launch(void* const* d_in, const int* in_sizes, int n_in,
                              void* d_out, int out_size) {
    (void)in_sizes; (void)n_in; (void)out_size;
    const float* memory  = (const float*)d_in[0];
    // d_in[1] memory_lengths unused (mask = None in reference)
    const float* teacher = (const float*)d_in[2];
    const float* pre_w1  = (const float*)d_in[3];
    const float* pre_w2  = (const float*)d_in[4];
    const float* q_wih   = (const float*)d_in[5];
    const float* q_whh   = (const float*)d_in[6];
    const float* q_bih   = (const float*)d_in[7];
    const float* q_bhh   = (const float*)d_in[8];
    const float* d_wih   = (const float*)d_in[9];
    const float* d_whh   = (const float*)d_in[10];
    const float* d_bih   = (const float*)d_in[11];
    const float* d_bhh   = (const float*)d_in[12];
    const float* attn_wq   = (const float*)d_in[13];
    const float* attn_wm   = (const float*)d_in[14];
    const float* attn_conv = (const float*)d_in[15];
    const float* attn_wloc = (const float*)d_in[16];
    const float* attn_v    = (const float*)d_in[17];
    const float* proj_w  = (const float*)d_in[18];
    const float* proj_b  = (const float*)d_in[19];
    const float* gate_w  = (const float*)d_in[20];
    const float* gate_b  = (const float*)d_in[21];

    float* out_mel   = (float*)d_out;
    float* out_align = out_mel + (size_t)B_ * T_ * NMELS;
    float* out_stop  = out_align + (size_t)B_ * T_ * L_;

    cudaFuncSetAttribute(decoder_kernel,
                         cudaFuncAttributeMaxDynamicSharedMemorySize, SMEM_BYTES);

    decoder_kernel<<<NBLK, NTHR, SMEM_BYTES>>>(
        memory, teacher, pre_w1, pre_w2,
        q_wih, q_whh, q_bih, q_bhh,
        d_wih, d_whh, d_bih, d_bhh,
        attn_wq, attn_conv, attn_wloc, attn_v, attn_wm,
        proj_w, proj_b, gate_w, gate_b,
        out_mel, out_align, out_stop);
}

// round 8
// speedup vs baseline: 2.1380x; 1.4531x over previous
#include <cuda_runtime.h>
#include <math.h>

#define B_    16
#define L_    400
#define T_    200
#define NMELS 80
#define ENC   512
#define PRE   256
#define QHD   1024
#define ATTN_ 128
#define NFILT 32
#define NBLK  148
#define NTHR  512
#define SMEM_BYTES 163840   // dLSTM staging: 16 * 2560 * 4

// ---- scratch (device globals; allocation forbidden) ----
__device__ __align__(16) float g_dec_ins[T_ * B_ * PRE];
__device__ __align__(16) float g_h1[B_ * T_ * PRE];
__device__ __align__(16) float g_pm[B_ * L_ * ATTN_];
__device__ __align__(16) float g_cl[B_ * L_ * NFILT];
__device__ __align__(16) float g_p[B_ * L_];          // exp(energy)
__device__ __align__(16) float g_psum[2][B_ * 8];     // per-tile partial sums
__device__ __align__(16) float g_pq[B_ * ATTN_];
__device__ __align__(16) float g_ctxraw[2][B_ * ENC]; // unnormalized context
__device__ __align__(16) float g_A[2][B_ * L_];       // cumulative attention
__device__ __align__(16) float g_qh[2][B_ * QHD];
__device__ __align__(16) float g_qc[B_ * QHD];
__device__ __align__(16) float g_dh[2][B_ * QHD];
__device__ __align__(16) float g_dc[B_ * QHD];
__device__ unsigned g_count;   // returns to 0 after every run
__device__ unsigned g_gen;     // monotonic

// ---- software grid barrier ----
__device__ __forceinline__ void grid_sync() {
    __syncthreads();
    if (threadIdx.x == 0) {
        volatile unsigned* vg = &g_gen;
        unsigned gen = *vg;
        __threadfence();
        if (atomicAdd(&g_count, 1u) == NBLK - 1) {
            g_count = 0u;
            __threadfence();
            atomicAdd(&g_gen, 1u);
        } else {
            while (*vg == gen) __nanosleep(32);
        }
        __threadfence();
    }
    __syncthreads();
}

__device__ __forceinline__ float sigmoidf_(float z) { return 1.f / (1.f + expf(-z)); }

// stage 16 rows (glen stride) into smem xs (KTOT stride) at column coff
__device__ __forceinline__ void stageT(float* xs, int KTOT, int coff,
                                       const float* __restrict__ src, int glen, int len) {
    int n4 = len >> 2;
    for (int idx = threadIdx.x; idx < 16 * n4; idx += NTHR) {
        int b = idx / n4, k4 = idx - b * n4;
        *(float4*)(xs + b * KTOT + coff + (k4 << 2)) =
            *(const float4*)(src + (size_t)b * glen + (k4 << 2));
    }
}
__device__ __forceinline__ void stage_scaled(float* xs, int KTOT, int coff,
                                             const float* __restrict__ src, int len,
                                             const float* sinv) {
    int n4 = len >> 2;
    for (int idx = threadIdx.x; idx < 16 * n4; idx += NTHR) {
        int b = idx / n4, k4 = idx - b * n4;
        float s = sinv[b];
        float4 v = *(const float4*)(src + (size_t)b * len + (k4 << 2));
        v.x *= s; v.y *= s; v.z *= s; v.w *= s;
        *(float4*)(xs + b * KTOT + coff + (k4 << 2)) = v;
    }
}
__device__ __forceinline__ void stage_zero(float* xs, int KTOT, int coff, int len) {
    int n4 = len >> 2;
    float4 z = {0.f, 0.f, 0.f, 0.f};
    for (int idx = threadIdx.x; idx < 16 * n4; idx += NTHR) {
        int b = idx / n4, k4 = idx - b * n4;
        *(float4*)(xs + b * KTOT + coff + (k4 << 2)) = z;
    }
}

// warp computes 2 rows x 16 batches, weight float4s double-buffered
__device__ __forceinline__ void gemv_pf2(const float* xs, int KTOT, int xoff, int nc,
                                         const float* __restrict__ w0,
                                         const float* __restrict__ w1,
                                         int lane, float acc0[16], float acc1[16]) {
    int l4 = lane << 2;
    float4 a = *(const float4*)(w0 + l4);
    float4 c = *(const float4*)(w1 + l4);
    for (int ch = 0; ch < nc; ++ch) {
        float4 an = {0.f,0.f,0.f,0.f}, cn = {0.f,0.f,0.f,0.f};
        if (ch + 1 < nc) {
            an = *(const float4*)(w0 + ((ch + 1) << 7) + l4);
            cn = *(const float4*)(w1 + ((ch + 1) << 7) + l4);
        }
        const float* xp = xs + xoff + (ch << 7) + l4;
        #pragma unroll
        for (int b = 0; b < 16; ++b) {
            float4 xv = *(const float4*)(xp + b * KTOT);
            acc0[b] += a.x * xv.x + a.y * xv.y + a.z * xv.z + a.w * xv.w;
            acc1[b] += c.x * xv.x + c.y * xv.y + c.z * xv.z + c.w * xv.w;
        }
        a = an; c = cn;
    }
}

// LSTM slice: block handles nu units (4*nu rows), warps straddle gates
__device__ __forceinline__ void lstm_phase(const float* xs, int KTOT, int kih,
        const float* __restrict__ wih, const float* __restrict__ whh,
        const float* __restrict__ bih, const float* __restrict__ bhh,
        float* __restrict__ ho, float* __restrict__ cb, int u0, int nu, float* shz) {
    int tid = threadIdx.x, lane = tid & 31, w = tid >> 5;
    if (w < 2 * nu) {
        int local0 = w * 2, local1 = local0 + 1;
        int g0 = local0 / nu, lu0 = local0 - g0 * nu;
        int g1 = local1 / nu, lu1 = local1 - g1 * nu;
        int r0 = g0 * 1024 + u0 + lu0, r1 = g1 * 1024 + u0 + lu1;
        float acc0[16], acc1[16];
        #pragma unroll
        for (int b = 0; b < 16; ++b) { acc0[b] = 0.f; acc1[b] = 0.f; }
        gemv_pf2(xs, KTOT, 0, kih >> 7,
                 wih + (size_t)r0 * kih, wih + (size_t)r1 * kih, lane, acc0, acc1);
        gemv_pf2(xs, KTOT, kih, 8,
                 whh + (size_t)r0 * QHD, whh + (size_t)r1 * QHD, lane, acc0, acc1);
        #pragma unroll
        for (int off = 16; off > 0; off >>= 1) {
            #pragma unroll
            for (int b = 0; b < 16; ++b) {
                acc0[b] += __shfl_xor_sync(0xffffffffu, acc0[b], off);
                acc1[b] += __shfl_xor_sync(0xffffffffu, acc1[b], off);
            }
        }
        if (lane < 16) {
            shz[local0 * 16 + lane] = acc0[lane];
            shz[local1 * 16 + lane] = acc1[lane];
        }
    }
    __syncthreads();
    if (tid < 16 * nu) {
        int b = tid & 15, ui = tid >> 4, u = u0 + ui;
        float zi = shz[(0 * nu + ui) * 16 + b] + bih[u]        + bhh[u];
        float zf = shz[(1 * nu + ui) * 16 + b] + bih[1024 + u] + bhh[1024 + u];
        float zg = shz[(2 * nu + ui) * 16 + b] + bih[2048 + u] + bhh[2048 + u];
        float zo = shz[(3 * nu + ui) * 16 + b] + bih[3072 + u] + bhh[3072 + u];
        float cc = sigmoidf_(zf) * cb[b * 1024 + u] + sigmoidf_(zi) * tanhf(zg);
        cb[b * 1024 + u] = cc;
        ho[b * 1024 + u] = sigmoidf_(zo) * tanhf(cc);
    }
    __syncthreads();
}

// pq: block covers (b = blk>>1, 64 rows); wq read once per step total
__device__ __forceinline__ void pq_phase(const float* __restrict__ wq,
                                         const float* __restrict__ hq_all,
                                         int blk, float* dsh) {
    int tid = threadIdx.x, lane = tid & 31, w = tid >> 5;
    int b = blk >> 1, rbase = (blk & 1) * 64;
    for (int i = tid; i < QHD; i += NTHR) dsh[i] = hq_all[(size_t)b * QHD + i];
    __syncthreads();
    int l4 = lane << 2;
    for (int pass = 0; pass < 2; ++pass) {
        int r0 = rbase + pass * 32 + w * 2, r1 = r0 + 1;
        const float* w0 = wq + (size_t)r0 * QHD;
        const float* w1 = wq + (size_t)r1 * QHD;
        float s0 = 0.f, s1 = 0.f;
        float4 a = *(const float4*)(w0 + l4);
        float4 c = *(const float4*)(w1 + l4);
        for (int ch = 0; ch < 8; ++ch) {
            float4 an = {0.f,0.f,0.f,0.f}, cn = {0.f,0.f,0.f,0.f};
            if (ch < 7) {
                an = *(const float4*)(w0 + ((ch + 1) << 7) + l4);
                cn = *(const float4*)(w1 + ((ch + 1) << 7) + l4);
            }
            float4 xv = *(const float4*)(dsh + (ch << 7) + l4);
            s0 += a.x * xv.x + a.y * xv.y + a.z * xv.z + a.w * xv.w;
            s1 += c.x * xv.x + c.y * xv.y + c.z * xv.z + c.w * xv.w;
            a = an; c = cn;
        }
        #pragma unroll
        for (int off = 16; off > 0; off >>= 1) {
            s0 += __shfl_xor_sync(0xffffffffu, s0, off);
            s1 += __shfl_xor_sync(0xffffffffu, s1, off);
        }
        if (lane == 0) { g_pq[b * ATTN_ + r0] = s0; g_pq[b * ATTN_ + r1] = s1; }
    }
    __syncthreads();
}

// conv task for step t (t>=1): normalize aw(t-1), update A, alignments, conv
__device__ __forceinline__ void conv_task(const float* __restrict__ convw,
                                          float* __restrict__ out_align,
                                          int t, int idx, float* dsh) {
    int tid = threadIdx.x;
    float* h0 = dsh;            // 132
    float* h1 = dsh + 132;      // 132
    float* cv = dsh + 264;      // 32*62
    int b = idx >> 2, l0 = (idx & 3) * 100;
    int pp = (t - 1) & 1, pc = t & 1;
    float s = 0.f;
    #pragma unroll
    for (int i = 0; i < 8; ++i) s += g_psum[pp][b * 8 + i];
    float invS = 1.f / s;
    for (int j = tid; j < 130; j += NTHR) {
        int pos = l0 - 15 + j;
        float pv = 0.f, anew = 0.f;
        if (pos >= 0 && pos < L_) {
            pv = g_p[b * L_ + pos] * invS;
            anew = g_A[pp][b * L_ + pos] + pv;
            if (pos >= l0 && pos < l0 + 100) {
                g_A[pc][b * L_ + pos] = anew;
                out_align[((size_t)b * T_ + (t - 1)) * L_ + pos] = pv;
            }
        }
        h0[j] = pv; h1[j] = anew;
    }
    for (int i = tid; i < NFILT * 62; i += NTHR) cv[i] = convw[i];
    __syncthreads();
    int f = tid & 31, lr = tid >> 5;
    const float* cf0 = cv + f * 62;
    const float* cf1 = cf0 + 31;
    for (int l = l0 + lr; l < l0 + 100; l += 16) {
        int base = l - l0;
        float acc = 0.f;
        #pragma unroll
        for (int k = 0; k < 31; ++k)
            acc += h0[base + k] * cf0[k] + h1[base + k] * cf1[k];
        g_cl[((size_t)b * L_ + l) * NFILT + f] = acc;
    }
    __syncthreads();
}

// energy + ctx partials for (b, 50-l tile)
__device__ __forceinline__ void energy_ctx_phase(
        const float* __restrict__ memory, const float* __restrict__ wloc,
        const float* __restrict__ av, int t, int blk, float* dsh) {
    int tid = threadIdx.x, lane = tid & 31, w = tid >> 5;
    int b = blk >> 3, tile = blk & 7, l0 = tile * 50;
    float* wlT = dsh;             // 4096 [f][a]
    float* pqs = dsh + 4096;      // 128
    float* vs  = dsh + 4224;      // 128
    float* sp  = dsh + 4352;      // 64
    float* cls = dsh + 4416;      // 16 x 32
    float* red = dsh + 4928;      // 16
    for (int i = tid; i < ATTN_ * NFILT; i += NTHR)
        wlT[(i & 31) * ATTN_ + (i >> 5)] = wloc[i];
    if (tid < ATTN_) { pqs[tid] = g_pq[b * ATTN_ + tid]; vs[tid] = av[tid]; }
    __syncthreads();
    float psum = 0.f;
    for (int l = l0 + w; l < l0 + 50; l += 16) {
        cls[w * 32 + lane] = g_cl[((size_t)b * L_ + l) * NFILT + lane];
        __syncwarp();
        const float* pmr = g_pm + ((size_t)b * L_ + l) * ATTN_;
        float s0 = pqs[lane]      + pmr[lane];
        float s1 = pqs[lane + 32] + pmr[lane + 32];
        float s2 = pqs[lane + 64] + pmr[lane + 64];
        float s3 = pqs[lane + 96] + pmr[lane + 96];
        #pragma unroll
        for (int f = 0; f < NFILT; ++f) {
            float clf = cls[w * 32 + f];
            const float* wr = wlT + f * ATTN_;
            s0 += clf * wr[lane];       s1 += clf * wr[lane + 32];
            s2 += clf * wr[lane + 64];  s3 += clf * wr[lane + 96];
        }
        float e = tanhf(s0) * vs[lane] + tanhf(s1) * vs[lane + 32] +
                  tanhf(s2) * vs[lane + 64] + tanhf(s3) * vs[lane + 96];
        #pragma unroll
        for (int off = 16; off > 0; off >>= 1) e += __shfl_xor_sync(0xffffffffu, e, off);
        if (lane == 0) {
            float p = expf(e);            // |e| <= sum|v| ~ 5: safe without max-sub
            g_p[b * L_ + l] = p;
            sp[l - l0] = p;
            psum += p;
        }
        __syncwarp();
    }
    if (lane == 0) red[w] = psum;
    __syncthreads();
    if (tid == 0) {
        float s = 0.f;
        #pragma unroll
        for (int i = 0; i < 16; ++i) s += red[i];
        g_psum[t & 1][b * 8 + tile] = s;
    }
    // ctx partial: thread = column
    int c = tid;
    const float* mp = memory + ((size_t)b * L_ + l0) * ENC + c;
    float acc = 0.f;
    #pragma unroll 5
    for (int j = 0; j < 50; ++j) acc += sp[j] * mp[(size_t)j * ENC];
    atomicAdd(&g_ctxraw[t & 1][b * ENC + c], acc);
    __syncthreads();
}

// output projection for step tprev (3 blocks x 32 rows)
__device__ __forceinline__ void out_proj(
        const float* __restrict__ proj_w, const float* __restrict__ proj_b,
        const float* __restrict__ gate_w, const float* __restrict__ gate_b,
        int tprev, int blkL, float* __restrict__ out_mel, float* __restrict__ out_stop,
        float* shz) {
    int tid = threadIdx.x, lane = tid & 31, w = tid >> 5;
    int par = tprev & 1;
    if (tid < 16) {
        float s = 0.f;
        #pragma unroll
        for (int i = 0; i < 8; ++i) s += g_psum[par][tid * 8 + i];
        shz[512 + tid] = 1.f / s;
    }
    __syncthreads();
    const float* dh = g_dh[(tprev + 1) & 1];
    const float* cr = g_ctxraw[par];
    int r0 = blkL * 32 + w * 2;
    for (int rr = 0; rr < 2; ++rr) {
        int r = r0 + rr;
        if (r > 80) break;
        const float* wr = (r < 80) ? proj_w + (size_t)r * (QHD + ENC) : gate_w;
        float accA[16], accB[16];
        #pragma unroll
        for (int b = 0; b < 16; ++b) { accA[b] = 0.f; accB[b] = 0.f; }
        for (int ch = 0; ch < 8; ++ch) {
            int k = (ch << 7) + (lane << 2);
            float4 a = *(const float4*)(wr + k);
            #pragma unroll
            for (int b = 0; b < 16; ++b) {
                float4 xv = *(const float4*)(dh + b * QHD + k);
                accA[b] += a.x * xv.x + a.y * xv.y + a.z * xv.z + a.w * xv.w;
            }
        }
        for (int ch = 0; ch < 4; ++ch) {
            int k = (ch << 7) + (lane << 2);
            float4 a = *(const float4*)(wr + QHD + k);
            #pragma unroll
            for (int b = 0; b < 16; ++b) {
                float4 xv = *(const float4*)(cr + b * ENC + k);
                accB[b] += a.x * xv.x + a.y * xv.y + a.z * xv.z + a.w * xv.w;
            }
        }
        #pragma unroll
        for (int off = 16; off > 0; off >>= 1) {
            #pragma unroll
            for (int b = 0; b < 16; ++b) {
                accA[b] += __shfl_xor_sync(0xffffffffu, accA[b], off);
                accB[b] += __shfl_xor_sync(0xffffffffu, accB[b], off);
            }
        }
        if (lane < 16) {
            int b = lane;
            float val = accA[b] + accB[b] * shz[512 + b];
            if (r < 80) out_mel[((size_t)b * T_ + tprev) * NMELS + r] = val + proj_b[r];
            else        out_stop[(size_t)b * T_ + tprev] = sigmoidf_(val + gate_b[0]);
        }
    }
    __syncthreads();
}

__global__ __launch_bounds__(NTHR, 1) void decoder_kernel(
    const float* __restrict__ memory, const float* __restrict__ teacher,
    const float* __restrict__ pre_w1, const float* __restrict__ pre_w2,
    const float* __restrict__ q_wih, const float* __restrict__ q_whh,
    const float* __restrict__ q_bih, const float* __restrict__ q_bhh,
    const float* __restrict__ d_wih, const float* __restrict__ d_whh,
    const float* __restrict__ d_bih, const float* __restrict__ d_bhh,
    const float* __restrict__ wq, const float* __restrict__ conv,
    const float* __restrict__ wloc, const float* __restrict__ av,
    const float* __restrict__ wm,
    const float* __restrict__ proj_w, const float* __restrict__ proj_b,
    const float* __restrict__ gate_w, const float* __restrict__ gate_b,
    float* __restrict__ out_mel, float* __restrict__ out_align,
    float* __restrict__ out_stop) {
    extern __shared__ __align__(16) float dsh[];
    __shared__ __align__(16) float shz[528];
    int blk = blockIdx.x, tid = threadIdx.x;
    int nu = (blk < 136) ? 7 : 6;
    int u0 = (blk < 136) ? blk * 7 : 952 + (blk - 136) * 6;

    // ---- init: zero state ----
    for (int i = blk * NTHR + tid; i < B_ * QHD; i += NBLK * NTHR) {
        g_qh[0][i] = 0.f; g_qc[i] = 0.f; g_dh[0][i] = 0.f; g_dc[i] = 0.f;
    }
    for (int i = blk * NTHR + tid; i < B_ * ENC; i += NBLK * NTHR) {
        g_ctxraw[0][i] = 0.f; g_ctxraw[1][i] = 0.f;
    }
    for (int i = blk * NTHR + tid; i < B_ * L_; i += NBLK * NTHR) {
        g_A[0][i] = 0.f; g_A[1][i] = 0.f;
    }
    for (int i = blk * NTHR + tid; i < B_ * L_ * NFILT; i += NBLK * NTHR) g_cl[i] = 0.f;
    for (int i = blk * NTHR + tid; i < B_ * PRE; i += NBLK * NTHR) g_dec_ins[i] = 0.f;

    // ---- prenet layer 1 ----
    for (int tile = blk; tile < 200; tile += NBLK) {
        __syncthreads();
        int r0 = tile * 16;
        for (int i = tid; i < 16 * NMELS; i += NTHR) dsh[i] = teacher[(size_t)r0 * NMELS + i];
        __syncthreads();
        int j = tid & 255, rh = tid >> 8;
        const float* wr = pre_w1 + (size_t)j * NMELS;
        for (int r = rh * 8; r < rh * 8 + 8; ++r) {
            float acc = 0.f;
            #pragma unroll
            for (int m = 0; m < NMELS; ++m) acc += dsh[r * NMELS + m] * wr[m];
            g_h1[(size_t)(r0 + r) * PRE + j] = fmaxf(acc, 0.f);
        }
    }
    grid_sync();

    // ---- prenet layer 2 + processed_memory ----
    for (int tt = blk; tt < 199; tt += NBLK) {
        int t = tt + 1;
        __syncthreads();
        for (int i = tid; i < 16 * PRE; i += NTHR)
            dsh[i] = g_h1[((size_t)(i >> 8) * T_ + (t - 1)) * PRE + (i & 255)];
        __syncthreads();
        int j = tid & 255, rh = tid >> 8;
        const float4* wr4 = (const float4*)(pre_w2 + (size_t)j * PRE);
        for (int bb = rh * 8; bb < rh * 8 + 8; ++bb) {
            const float4* sx4 = (const float4*)(dsh + bb * PRE);
            float acc = 0.f;
            #pragma unroll 8
            for (int k = 0; k < PRE / 4; ++k) {
                float4 a = wr4[k], x = sx4[k];
                acc += a.x * x.x + a.y * x.y + a.z * x.z + a.w * x.w;
            }
            g_dec_ins[((size_t)t * B_ + bb) * PRE + j] = fmaxf(acc, 0.f);
        }
    }
    for (int tile = blk; tile < 400; tile += NBLK) {
        __syncthreads();
        int r0 = tile * 16;
        for (int i = tid; i < 16 * ENC; i += NTHR) dsh[i] = memory[(size_t)r0 * ENC + i];
        __syncthreads();
        int a = tid & 127, q = tid >> 7;
        const float4* wr4 = (const float4*)(wm + (size_t)a * ENC);
        for (int r = q * 4; r < q * 4 + 4; ++r) {
            const float4* sx4 = (const float4*)(dsh + r * ENC);
            float acc = 0.f;
            #pragma unroll 8
            for (int k = 0; k < ENC / 4; ++k) {
                float4 aa = wr4[k], x = sx4[k];
                acc += aa.x * x.x + aa.y * x.y + aa.z * x.z + aa.w * x.w;
            }
            g_pm[(size_t)(r0 + r) * ATTN_ + a] = acc;
        }
    }
    grid_sync();

    // ---- decode loop: 4 phases/step ----
    for (int t = 0; t < T_; ++t) {
        // P_A: qLSTM on all 148 blocks
        {
            if (t > 0) {
                if (tid < 16) {
                    float s = 0.f;
                    #pragma unroll
                    for (int i = 0; i < 8; ++i) s += g_psum[(t + 1) & 1][tid * 8 + i];
                    shz[512 + tid] = 1.f / s;
                }
                __syncthreads();
            }
            stageT(dsh, 1792, 0, g_dec_ins + (size_t)t * B_ * PRE, PRE, PRE);
            if (t > 0) stage_scaled(dsh, 1792, 256, g_ctxraw[(t + 1) & 1], ENC, shz + 512);
            else       stage_zero(dsh, 1792, 256, ENC);
            stageT(dsh, 1792, 768, g_qh[t & 1], QHD, QHD);
            __syncthreads();
            lstm_phase(dsh, 1792, 768, q_wih, q_whh, q_bih, q_bhh,
                       g_qh[(t + 1) & 1], g_qc, u0, nu, shz);
        }
        grid_sync();
        // P_B1: pq (0-31) | conv (32-95) | out_proj(t-1) (96-98)
        if (blk < 32) {
            pq_phase(wq, g_qh[(t + 1) & 1], blk, dsh);
        } else if (blk < 96) {
            if (t > 0) conv_task(conv, out_align, t, blk - 32, dsh);
        } else if (blk < 99) {
            if (t > 0) out_proj(proj_w, proj_b, gate_w, gate_b, t - 1, blk - 96,
                                out_mel, out_stop, shz);
        }
        grid_sync();
        // P_B2: energies + ctx partials
        if (blk < 128) energy_ctx_phase(memory, wloc, av, t, blk, dsh);
        grid_sync();
        // P_D: dLSTM on all 148 blocks (+ zero next ctxraw by spare warps)
        {
            if (blk < 16 && tid >= 448) {
                int i0 = blk * 512 + (tid - 448) * 8;
                #pragma unroll
                for (int k = 0; k < 8; ++k) g_ctxraw[(t + 1) & 1][i0 + k] = 0.f;
            }
            if (tid < 16) {
                float s = 0.f;
                #pragma unroll
                for (int i = 0; i < 8; ++i) s += g_psum[t & 1][tid * 8 + i];
                shz[512 + tid] = 1.f / s;
            }
            __syncthreads();
            stage_scaled(dsh, 2560, 0, g_ctxraw[t & 1], ENC, shz + 512);
            stageT(dsh, 2560, 512,  g_qh[(t + 1) & 1], QHD, QHD);
            stageT(dsh, 2560, 1536, g_dh[t & 1], QHD, QHD);
            __syncthreads();
            lstm_phase(dsh, 2560, 1536, d_wih, d_whh, d_bih, d_bhh,
                       g_dh[(t + 1) & 1], g_dc, u0, nu, shz);
        }
        grid_sync();
    }
    // finals: out_proj(T-1) + alignments(T-1)
    if (blk >= 96 && blk < 99) {
        out_proj(proj_w, proj_b, gate_w, gate_b, T_ - 1, blk - 96,
                 out_mel, out_stop, shz);
    } else if (blk >= 32 && blk < 96) {
        int idx = blk - 32;
        int b = idx >> 2, l0 = (idx & 3) * 100;
        float s = 0.f;
        #pragma unroll
        for (int i = 0; i < 8; ++i) s += g_psum[(T_ - 1) & 1][b * 8 + i];
        float invS = 1.f / s;
        for (int j = tid; j < 100; j += NTHR) {
            int l = l0 + j;
            out_align[((size_t)b * T_ + (T_ - 1)) * L_ + l] = g_p[b * L_ + l] * invS;
        }
    }
}

extern "C" void kernel_launch(void* const* d_in, const int* in_sizes, int n_in,
                              void* d_out, int out_size) {
    (void)in_sizes; (void)n_in; (void)out_size;
    const float* memory  = (const float*)d_in[0];
    // d_in[1] memory_lengths unused (mask = None in reference)
    const float* teacher = (const float*)d_in[2];
    const float* pre_w1  = (const float*)d_in[3];
    const float* pre_w2  = (const float*)d_in[4];
    const float* q_wih   = (const float*)d_in[5];
    const float* q_whh   = (const float*)d_in[6];
    const float* q_bih   = (const float*)d_in[7];
    const float* q_bhh   = (const float*)d_in[8];
    const float* d_wih   = (const float*)d_in[9];
    const float* d_whh   = (const float*)d_in[10];
    const float* d_bih   = (const float*)d_in[11];
    const float* d_bhh   = (const float*)d_in[12];
    const float* attn_wq   = (const float*)d_in[13];
    const float* attn_wm   = (const float*)d_in[14];
    const float* attn_conv = (const float*)d_in[15];
    const float* attn_wloc = (const float*)d_in[16];
    const float* attn_v    = (const float*)d_in[17];
    const float* proj_w  = (const float*)d_in[18];
    const float* proj_b  = (const float*)d_in[19];
    const float* gate_w  = (const float*)d_in[20];
    const float* gate_b  = (const float*)d_in[21];

    float* out_mel   = (float*)d_out;
    float* out_align = out_mel + (size_t)B_ * T_ * NMELS;
    float* out_stop  = out_align + (size_t)B_ * T_ * L_;

    cudaFuncSetAttribute(decoder_kernel,
                         cudaFuncAttributeMaxDynamicSharedMemorySize, SMEM_BYTES);

    decoder_kernel<<<NBLK, NTHR, SMEM_BYTES>>>(
        memory, teacher, pre_w1, pre_w2,
        q_wih, q_whh, q_bih, q_bhh,
        d_wih, d_whh, d_bih, d_bhh,
        attn_wq, attn_conv, attn_wloc, attn_v, attn_wm,
        proj_w, proj_b, gate_w, gate_b,
        out_mel, out_align, out_stop);
}